// round 15
// baseline (speedup 1.0000x reference)
#include <cuda_runtime.h>
#include <cuda_bf16.h>
#include <cstdint>

#define TLEN 4096
#define KJ   24
#define NBATCH 4
#define MTOT (NBATCH * KJ * TLEN)   // 393216 token rows
#define TPAD 136                     // bf16 elems per smem tile row (272B)

// ---------------- device scratch ----------------
__device__ __align__(256) __nv_bfloat16 g_tok_hi[(size_t)MTOT * 128];
__device__ __align__(256) __nv_bfloat16 g_tok_lo[(size_t)MTOT * 128];
__device__ __align__(256) float         g_wc[128 * 128];
__device__ __align__(256) float         g_bc[128];
__device__ __align__(256) __nv_bfloat16 g_wtok_hi[128 * 128], g_wtok_lo[128 * 128];
__device__ __align__(256) __nv_bfloat16 g_wqkv_hi[384 * 128], g_wqkv_lo[384 * 128];
__device__ __align__(256) __nv_bfloat16 g_wc_hi[128 * 128],   g_wc_lo[128 * 128];

typedef unsigned long long u64;

// ---------------- helpers ----------------
static __device__ __forceinline__ uint32_t s2u(const void* p) {
    uint32_t a;
    asm("{ .reg .u64 t; cvta.to.shared.u64 t, %1; cvt.u32.u64 %0, t; }" : "=r"(a) : "l"(p));
    return a;
}
static __device__ __forceinline__ void cp16(uint32_t dst, const void* src) {
    asm volatile("cp.async.cg.shared.global [%0], [%1], 16;" :: "r"(dst), "l"(src));
}
static __device__ __forceinline__ void cp_commit() {
    asm volatile("cp.async.commit_group;");
}
static __device__ __forceinline__ void cp_wait0() {
    asm volatile("cp.async.wait_group 0;" ::: "memory");
}
template<int N>
static __device__ __forceinline__ void cp_waitg() {
    asm volatile("cp.async.wait_group %0;" :: "n"(N) : "memory");
}
static __device__ __forceinline__ void split_bf(float v, uint16_t& h, uint16_t& l) {
    __nv_bfloat16 hb = __float2bfloat16(v);
    float r = v - __bfloat162float(hb);
    h = __bfloat16_as_ushort(hb);
    l = __bfloat16_as_ushort(__float2bfloat16(r));
}
static __device__ __forceinline__ void fma2(u64& d, u64 a, u64 b) {
    asm("fma.rn.f32x2 %0, %1, %2, %0;" : "+l"(d) : "l"(a), "l"(b));
}
static __device__ __forceinline__ void up2(u64 v, float& a, float& b) {
    asm("mov.b64 {%0, %1}, %2;" : "=f"(a), "=f"(b) : "l"(v));
}
static __device__ __forceinline__ void ldsm4(uint32_t* r, uint32_t addr) {
    asm volatile("ldmatrix.sync.aligned.m8n8.x4.shared.b16 {%0,%1,%2,%3}, [%4];"
                 : "=r"(r[0]), "=r"(r[1]), "=r"(r[2]), "=r"(r[3]) : "r"(addr));
}
static __device__ __forceinline__ void mma16816(float* c, const uint32_t* a, const uint32_t* b) {
    asm volatile("mma.sync.aligned.m16n8k16.row.col.f32.bf16.bf16.f32 "
                 "{%0,%1,%2,%3}, {%4,%5,%6,%7}, {%8,%9}, {%0,%1,%2,%3};"
                 : "+f"(c[0]), "+f"(c[1]), "+f"(c[2]), "+f"(c[3])
                 : "r"(a[0]), "r"(a[1]), "r"(a[2]), "r"(a[3]), "r"(b[0]), "r"(b[1]));
}

// one K=128 pass of a (MT*16)x(NT*16) warp tile
template<int MT, int NT>
static __device__ __forceinline__ void gemm_pass(uint32_t aBase, uint32_t bBase,
                                                 float acc[MT][2 * NT][4],
                                                 int lane, int m0, int n0) {
    const int ar = m0 + (lane & 15), ac = 8 * (lane >> 4);
    const int br = (lane & 7) + 8 * (lane >> 4), bc = 8 * ((lane >> 3) & 1);
    #pragma unroll
    for (int ks = 0; ks < 8; ks++) {
        uint32_t a[MT][4], b[NT][4];
        #pragma unroll
        for (int mt = 0; mt < MT; mt++)
            ldsm4(a[mt], aBase + (uint32_t)((ar + mt * 16) * TPAD + ks * 16 + ac) * 2);
        #pragma unroll
        for (int nt = 0; nt < NT; nt++)
            ldsm4(b[nt], bBase + (uint32_t)((n0 + nt * 16 + br) * TPAD + ks * 16 + bc) * 2);
        #pragma unroll
        for (int mt = 0; mt < MT; mt++)
            #pragma unroll
            for (int nt = 0; nt < NT; nt++) {
                mma16816(acc[mt][nt * 2],     a[mt], &b[nt][0]);
                mma16816(acc[mt][nt * 2 + 1], a[mt], &b[nt][2]);
            }
    }
}
template<int MT, int NT>
static __device__ __forceinline__ void gemm3(uint32_t aHi, uint32_t aLo, uint32_t bHi,
                                             uint32_t bLo, float acc[MT][2 * NT][4],
                                             int lane, int m0, int n0) {
    gemm_pass<MT, NT>(aHi, bHi, acc, lane, m0, n0);
    gemm_pass<MT, NT>(aHi, bLo, acc, lane, m0, n0);
    gemm_pass<MT, NT>(aLo, bHi, acc, lane, m0, n0);
}
// write C fragments (raw) into f32 staging, stride 129
template<int MT, int NT>
static __device__ __forceinline__ void stash(float* stg, const float acc[MT][2 * NT][4],
                                             int lane, int m0, int n0) {
    const int r = m0 + (lane >> 2), cq = (lane & 3) * 2;
    #pragma unroll
    for (int mt = 0; mt < MT; mt++)
        #pragma unroll
        for (int n8 = 0; n8 < 2 * NT; n8++) {
            const float* c = acc[mt][n8];
            int row = r + mt * 16, col = n0 + n8 * 8 + cq;
            stg[row * 129 + col]           = c[0];
            stg[row * 129 + col + 1]       = c[1];
            stg[(row + 8) * 129 + col]     = c[2];
            stg[(row + 8) * 129 + col + 1] = c[3];
        }
}

// ================= K0a: Wc = W_proj @ W_from, bc = b_proj@W_from + b_from =========
__global__ __launch_bounds__(256) void k0a(const float* __restrict__ Wp,
                                           const float* __restrict__ Wf,
                                           const float* __restrict__ bp,
                                           const float* __restrict__ bf) {
    __shared__ float swp[32 * 128];
    const int tid = threadIdx.x, r0 = blockIdx.x * 32;
    for (int i = tid; i < 32 * 128; i += 256) swp[i] = Wp[(r0 + (i >> 7)) * 128 + (i & 127)];
    __syncthreads();
    const int n = tid & 127, rb = tid >> 7;
    float acc[16];
    #pragma unroll
    for (int q = 0; q < 16; q++) acc[q] = 0.f;
    for (int m = 0; m < 128; m++) {
        float wf = Wf[m * 128 + n];
        #pragma unroll
        for (int q = 0; q < 16; q++) acc[q] += swp[(rb * 16 + q) * 128 + m] * wf;
    }
    #pragma unroll
    for (int q = 0; q < 16; q++) g_wc[(r0 + rb * 16 + q) * 128 + n] = acc[q];
    if (blockIdx.x == 0 && tid < 128) {
        float a = bf[tid];
        for (int m = 0; m < 128; m++) a += bp[m] * Wf[m * 128 + tid];
        g_bc[tid] = a;
    }
}

// ================= K0b: transpose + hi/lo split weights =================
__global__ __launch_bounds__(256) void k0b(const float* __restrict__ Wt,
                                           const float* __restrict__ Wq) {
    const int i = blockIdx.x * 256 + threadIdx.x;
    uint16_t h, l;
    if (i < 16384) {
        int n = i >> 7, k = i & 127;
        split_bf(Wt[k * 128 + n], h, l);
        g_wtok_hi[i] = __ushort_as_bfloat16(h); g_wtok_lo[i] = __ushort_as_bfloat16(l);
        split_bf(g_wc[k * 128 + n], h, l);
        g_wc_hi[i] = __ushort_as_bfloat16(h);   g_wc_lo[i] = __ushort_as_bfloat16(l);
    }
    if (i < 49152) {
        int n = i >> 7, k = i & 127;
        split_bf(Wq[k * 384 + n], h, l);
        g_wqkv_hi[i] = __ushort_as_bfloat16(h); g_wqkv_lo[i] = __ushort_as_bfloat16(l);
    }
}

// ================= K1: tok = x^T @ W_tok + b, RMSNorm, split-store ===============
#define K1_BIAS 0
#define K1_G    512
#define K1_AXS  1024
#define K1_AHI  35840
#define K1_ALO  53248
#define K1_BHI  70656
#define K1_BLO  88064
#define K1_SMEM 105472

__global__ __launch_bounds__(256, 2)
void k1_tok(const float* __restrict__ x, const float* __restrict__ b_tok,
            const float* __restrict__ g_norm) {
    extern __shared__ char sm[];
    const int tid = threadIdx.x, warp = tid >> 5, lane = tid & 31;
    const int b = blockIdx.z, kj = blockIdx.y, t0 = blockIdx.x * 64;
    const uint32_t sb = s2u(sm);

    for (int idx = tid; idx < 2048; idx += 256) {
        int c = idx >> 4, t16 = (idx & 15) * 4;
        const float* src = x + ((size_t)(b * 3072 + kj * 128 + c)) * 4096 + t0 + t16;
        cp16(sb + K1_AXS + (uint32_t)(c * 68 + t16) * 4, src);
    }
    for (int idx = tid; idx < 1024; idx += 256) {
        int row = idx >> 4, c8 = (idx & 15) * 8;
        uint32_t off = (uint32_t)(row * TPAD + c8) * 2;
        cp16(sb + K1_BHI + off, g_wtok_hi + row * 128 + c8);
        cp16(sb + K1_BLO + off, g_wtok_lo + row * 128 + c8);
    }
    if (tid < 128) {
        *(float*)(sm + K1_BIAS + tid * 4) = b_tok[tid];
        *(float*)(sm + K1_G + tid * 4)    = g_norm[tid];
    }
    cp_commit();
    cp_wait0();
    __syncthreads();

    {
        const int t = tid & 63, quarter = tid >> 6;
        const float* ax = (const float*)(sm + K1_AXS);
        for (int c4 = quarter * 8; c4 < quarter * 8 + 8; c4++) {
            int c = c4 * 4;
            float v0 = ax[(c + 0) * 68 + t], v1 = ax[(c + 1) * 68 + t];
            float v2 = ax[(c + 2) * 68 + t], v3 = ax[(c + 3) * 68 + t];
            uint16_t h0, l0, h1, l1, h2, l2, h3, l3;
            split_bf(v0, h0, l0); split_bf(v1, h1, l1);
            split_bf(v2, h2, l2); split_bf(v3, h3, l3);
            uint32_t off = (uint32_t)(t * TPAD + c) * 2;
            *(uint2*)(sm + K1_AHI + off) = make_uint2(h0 | ((uint32_t)h1 << 16), h2 | ((uint32_t)h3 << 16));
            *(uint2*)(sm + K1_ALO + off) = make_uint2(l0 | ((uint32_t)l1 << 16), l2 | ((uint32_t)l3 << 16));
        }
    }
    __syncthreads();

    const int m0 = (warp & 3) * 16, n0 = (warp >> 2) * 32;
    for (int nc = 0; nc < 2; nc++) {
        float acc[1][4][4];
        #pragma unroll
        for (int j = 0; j < 4; j++)
            #pragma unroll
            for (int q = 0; q < 4; q++) acc[0][j][q] = 0.f;
        gemm3<1, 2>(sb + K1_AHI, sb + K1_ALO, sb + K1_BHI, sb + K1_BLO, acc, lane, m0, n0);
        stash<1, 2>((float*)(sm + K1_AXS), acc, lane, m0, nc * 64 + n0);
        if (nc == 0) {
            __syncthreads();
            for (int idx = tid; idx < 1024; idx += 256) {
                int row = idx >> 4, c8 = (idx & 15) * 8;
                uint32_t off = (uint32_t)(row * TPAD + c8) * 2;
                cp16(sb + K1_BHI + off, g_wtok_hi + (64 + row) * 128 + c8);
                cp16(sb + K1_BLO + off, g_wtok_lo + (64 + row) * 128 + c8);
            }
            cp_commit();
            cp_wait0();
            __syncthreads();
        }
    }
    __syncthreads();

    uint32_t* shi = (uint32_t*)(sm + K1_AHI);
    uint32_t* slo = (uint32_t*)(sm + K1_ALO);
    {
        const int row = tid >> 2, sub = tid & 3;
        const float* stg  = (const float*)(sm + K1_AXS);
        const float* bias = (const float*)(sm + K1_BIAS);
        const float* gw   = (const float*)(sm + K1_G);
        float ss = 0.f;
        #pragma unroll 8
        for (int c = sub * 32; c < sub * 32 + 32; c++) {
            float v = stg[row * 129 + c] + bias[c];
            ss += v * v;
        }
        ss += __shfl_xor_sync(0xffffffffu, ss, 1);
        ss += __shfl_xor_sync(0xffffffffu, ss, 2);
        float inv = rsqrtf(ss * (1.0f / 128.0f) + 1e-5f);
        #pragma unroll 4
        for (int c2 = 0; c2 < 16; c2++) {
            int c = sub * 32 + c2 * 2;
            float v0 = (stg[row * 129 + c]     + bias[c])     * inv * gw[c];
            float v1 = (stg[row * 129 + c + 1] + bias[c + 1]) * inv * gw[c + 1];
            uint16_t h0, l0, h1, l1;
            split_bf(v0, h0, l0); split_bf(v1, h1, l1);
            shi[row * 65 + sub * 16 + c2] = h0 | ((uint32_t)h1 << 16);
            slo[row * 65 + sub * 16 + c2] = l0 | ((uint32_t)l1 << 16);
        }
    }
    __syncthreads();
    {
        uint32_t* dhi = (uint32_t*)g_tok_hi;
        uint32_t* dlo = (uint32_t*)g_tok_lo;
        for (int idx = tid; idx < 4096; idx += 256) {
            int row = idx >> 6, w = idx & 63;
            size_t rid = ((size_t)b * 4096 + t0 + row) * 24 + kj;
            dhi[rid * 64 + w] = shi[row * 65 + w];
            dlo[rid * 64 + w] = slo[row * 65 + w];
        }
    }
}

// ================= K234: fused qkv GEMM + attention + proj/from GEMM + output =====
// M = 96 rows = 4 complete t-groups per CTA. 384 threads, 1 CTA/SM.
#define QS 386
#define PRS 52
#define J_BIAS 0                     // 384 f32 (b_qkv; later bc)
#define J_S1   1536                  // B slot1 / A_hi / probs / ao_lo tile [96][TPAD]=26112
#define J_ALO  27648                 // A_lo tile / ao_hi tile [96][TPAD] = 26112
#define J_S0   53760                 // B slot0 [64][TPAD] = 17408
#define J_QKV  71168                 // f32 [96][QS] = 148224 ; tail: WC tiles + staging
#define K23_SMEM 219392
#define J_PROBS J_S1
#define J_WCHI J_QKV                 // [128][TPAD] = 34816
#define J_WCLO (J_QKV + 34816)
#define J_STG  (J_QKV + 69632)       // f32 [96][129] = 49536

__global__ __launch_bounds__(384, 1)
void k234(const float* __restrict__ x, const float* __restrict__ b_qkv,
          float* __restrict__ out) {
    extern __shared__ char sm[];
    const int tid = threadIdx.x, warp = tid >> 5, lane = tid & 31;
    const int b = blockIdx.y, t0 = blockIdx.x * 4;
    const size_t rid0 = ((size_t)b * 4096 + t0) * 24;
    const uint32_t sb = s2u(sm);

    // load A tiles (A_hi -> slot1 region, A_lo) + B_hi(chunk0) -> slot0 + bias
    for (int idx = tid; idx < 1536; idx += 384) {
        int row = idx >> 4, c8 = (idx & 15) * 8;
        uint32_t off = (uint32_t)(row * TPAD + c8) * 2;
        cp16(sb + J_S1 + off,  g_tok_hi + (rid0 + row) * 128 + c8);
        cp16(sb + J_ALO + off, g_tok_lo + (rid0 + row) * 128 + c8);
    }
    for (int idx = tid; idx < 1024; idx += 384) {
        int row = idx >> 4, c8 = (idx & 15) * 8;
        cp16(sb + J_S0 + (uint32_t)(row * TPAD + c8) * 2, g_wqkv_hi + row * 128 + c8);
    }
    *(float*)(sm + J_BIAS + tid * 4) = b_qkv[tid];
    cp_commit();
    cp_wait0();
    __syncthreads();

    // 12 warps = 3M(32) x 4N(16)
    const int m0 = (warp % 3) * 32, n0 = (warp / 3) * 16;
    const int ar = m0 + (lane & 15), ac = 8 * (lane >> 4);
    const int br = (lane & 7) + 8 * (lane >> 4), bc = 8 * ((lane >> 3) & 1);
    float* qkv = (float*)(sm + J_QKV);
    const float* bias = (const float*)(sm + J_BIAS);

    // hoist A_hi fragments (64 regs) from slot1 region, then free it for B ring
    uint32_t ahi[2][8][4];
    #pragma unroll
    for (int ks = 0; ks < 8; ks++) {
        ldsm4(ahi[0][ks], sb + J_S1 + (uint32_t)(ar * TPAD + ks * 16 + ac) * 2);
        ldsm4(ahi[1][ks], sb + J_S1 + (uint32_t)((ar + 16) * TPAD + ks * 16 + ac) * 2);
    }
    __syncthreads();   // all warps done reading A_hi smem

    // issue lo0 -> slot1 (overlaps chunk0 pass1/2)
    for (int idx = tid; idx < 1024; idx += 384) {
        int row = idx >> 4, c8 = (idx & 15) * 8;
        cp16(sb + J_S1 + (uint32_t)(row * TPAD + c8) * 2, g_wqkv_lo + row * 128 + c8);
    }
    cp_commit();

    for (int nc = 0; nc < 6; nc++) {
        if (nc > 0) {
            cp_waitg<1>();      // hi(nc) landed in slot0
            __syncthreads();
        }

        float acc[2][2][4];
        #pragma unroll
        for (int i = 0; i < 2; i++)
            #pragma unroll
            for (int j = 0; j < 2; j++)
                #pragma unroll
                for (int q = 0; q < 4; q++) acc[i][j][q] = 0.f;

        // pass1: hi*hi (A from regs, B slot0)
        #pragma unroll
        for (int ks = 0; ks < 8; ks++) {
            uint32_t bfr[4];
            ldsm4(bfr, sb + J_S0 + (uint32_t)((n0 + br) * TPAD + ks * 16 + bc) * 2);
            mma16816(acc[0][0], ahi[0][ks], &bfr[0]);
            mma16816(acc[0][1], ahi[0][ks], &bfr[2]);
            mma16816(acc[1][0], ahi[1][ks], &bfr[0]);
            mma16816(acc[1][1], ahi[1][ks], &bfr[2]);
        }
        // pass2: lo*hi (A_lo smem, B slot0)
        #pragma unroll
        for (int ks = 0; ks < 8; ks++) {
            uint32_t a0[4], a1[4], bfr[4];
            ldsm4(a0, sb + J_ALO + (uint32_t)(ar * TPAD + ks * 16 + ac) * 2);
            ldsm4(a1, sb + J_ALO + (uint32_t)((ar + 16) * TPAD + ks * 16 + ac) * 2);
            ldsm4(bfr, sb + J_S0 + (uint32_t)((n0 + br) * TPAD + ks * 16 + bc) * 2);
            mma16816(acc[0][0], a0, &bfr[0]);
            mma16816(acc[0][1], a0, &bfr[2]);
            mma16816(acc[1][0], a1, &bfr[0]);
            mma16816(acc[1][1], a1, &bfr[2]);
        }
        __syncthreads();       // all warps done with slot0

        if (nc < 5) {          // prefetch hi(nc+1) -> slot0, overlaps pass3
            for (int idx = tid; idx < 1024; idx += 384) {
                int row = idx >> 4, c8 = (idx & 15) * 8;
                cp16(sb + J_S0 + (uint32_t)(row * TPAD + c8) * 2,
                     g_wqkv_hi + ((nc + 1) * 64 + row) * 128 + c8);
            }
            cp_commit();
            cp_waitg<1>();     // lo(nc) landed in slot1
        } else {
            cp_waitg<0>();     // lo(5) landed
        }
        __syncthreads();

        // pass3: hi*lo (A from regs, B slot1)
        #pragma unroll
        for (int ks = 0; ks < 8; ks++) {
            uint32_t bfr[4];
            ldsm4(bfr, sb + J_S1 + (uint32_t)((n0 + br) * TPAD + ks * 16 + bc) * 2);
            mma16816(acc[0][0], ahi[0][ks], &bfr[0]);
            mma16816(acc[0][1], ahi[0][ks], &bfr[2]);
            mma16816(acc[1][0], ahi[1][ks], &bfr[0]);
            mma16816(acc[1][1], ahi[1][ks], &bfr[2]);
        }

        // epilogue -> qkv smem (+bias)
        {
            const int r = m0 + (lane >> 2), cq = (lane & 3) * 2;
            #pragma unroll
            for (int mt = 0; mt < 2; mt++)
                #pragma unroll
                for (int n8 = 0; n8 < 2; n8++) {
                    const float* c = acc[mt][n8];
                    int col = nc * 64 + n0 + n8 * 8 + cq;
                    int row = r + mt * 16;
                    qkv[row * QS + col]           = c[0] + bias[col];
                    qkv[row * QS + col + 1]       = c[1] + bias[col + 1];
                    qkv[(row + 8) * QS + col]     = c[2] + bias[col];
                    qkv[(row + 8) * QS + col + 1] = c[3] + bias[col + 1];
                }
        }
        __syncthreads();       // all warps done with slot1

        if (nc < 5) {          // prefetch lo(nc+1) -> slot1
            for (int idx = tid; idx < 1024; idx += 384) {
                int row = idx >> 4, c8 = (idx & 15) * 8;
                cp16(sb + J_S1 + (uint32_t)(row * TPAD + c8) * 2,
                     g_wqkv_lo + ((nc + 1) * 64 + row) * 128 + c8);
            }
            cp_commit();
        }
    }

    // ---- attention (probs overlay slot1 region) ----
    float* probs = (float*)(sm + J_PROBS);

    // scores: 2q x 4k tiles; 4 tl x 12 x 6 = 288 tiles
    if (tid < 288) {
        int tl = tid / 72, rem = tid - tl * 72;
        int ti = rem / 6, tj = rem - ti * 6;
        int i = 2 * ti, j = 4 * tj;
        const u64* q0 = reinterpret_cast<const u64*>(qkv + (tl * 24 + i) * QS);
        const u64* q1 = reinterpret_cast<const u64*>(qkv + (tl * 24 + i + 1) * QS);
        const u64* k0 = reinterpret_cast<const u64*>(qkv + (tl * 24 + j) * QS + 128);
        const u64* k1 = reinterpret_cast<const u64*>(qkv + (tl * 24 + j + 1) * QS + 128);
        const u64* k2 = reinterpret_cast<const u64*>(qkv + (tl * 24 + j + 2) * QS + 128);
        const u64* k3 = reinterpret_cast<const u64*>(qkv + (tl * 24 + j + 3) * QS + 128);
        u64 a0[4] = {0ull, 0ull, 0ull, 0ull};
        u64 a1[4] = {0ull, 0ull, 0ull, 0ull};
        #pragma unroll 8
        for (int c2 = 0; c2 < 64; c2++) {
            u64 qa = q0[c2], qb = q1[c2];
            u64 k0v = k0[c2], k1v = k1[c2], k2v = k2[c2], k3v = k3[c2];
            fma2(a0[0], qa, k0v); fma2(a0[1], qa, k1v);
            fma2(a0[2], qa, k2v); fma2(a0[3], qa, k3v);
            fma2(a1[0], qb, k0v); fma2(a1[1], qb, k1v);
            fma2(a1[2], qb, k2v); fma2(a1[3], qb, k3v);
        }
        const float SC = 0.08838834764831845f;
        float* pr = probs + (tl * 24 + i) * PRS;
        float s0, s1;
        #pragma unroll
        for (int jj = 0; jj < 4; jj++) {
            up2(a0[jj], s0, s1); pr[2 * (j + jj)]       = (s0 + s1) * SC;
            up2(a1[jj], s0, s1); pr[PRS + 2 * (j + jj)] = (s0 + s1) * SC;
        }
    }
    __syncthreads();

    if (tid < 96) {
        int tl = tid / 24, i = tid - tl * 24;
        float* pr = probs + (tl * 24 + i) * PRS;
        float m = pr[0];
        #pragma unroll
        for (int j = 1; j < 24; j++) m = fmaxf(m, pr[2 * j]);
        float s = 0.f, e[24];
        #pragma unroll
        for (int j = 0; j < 24; j++) { e[j] = __expf(pr[2 * j] - m); s += e[j]; }
        float inv = 1.0f / s;
        #pragma unroll
        for (int j = 0; j < 24; j++) {
            float p = e[j] * inv;
            *reinterpret_cast<float2*>(pr + 2 * j) = make_float2(p, p);
        }
    }
    __syncthreads();

    // AV: 12 warps: tl = warp/3, 8 joints per warp; probs loaded as dup pairs
    u64 av[8][2];
    {
        const int tl = warp / 3, i0 = (warp % 3) * 8, d0 = lane * 4;
        #pragma unroll
        for (int ii = 0; ii < 8; ii++) { av[ii][0] = 0ull; av[ii][1] = 0ull; }
        const float* pr0 = probs + (tl * 24 + i0) * PRS;
        #pragma unroll 3
        for (int j2 = 0; j2 < 12; j2++) {
            const u64* vp0 = reinterpret_cast<const u64*>(qkv + (tl * 24 + 2 * j2) * QS + 256 + d0);
            const u64* vp1 = reinterpret_cast<const u64*>(qkv + (tl * 24 + 2 * j2 + 1) * QS + 256 + d0);
            u64 va0 = vp0[0], vb0 = vp0[1];
            u64 va1 = vp1[0], vb1 = vp1[1];
            #pragma unroll
            for (int ii = 0; ii < 8; ii++) {
                ulonglong2 p = *reinterpret_cast<const ulonglong2*>(pr0 + ii * PRS + 4 * j2);
                fma2(av[ii][0], p.x, va0); fma2(av[ii][1], p.x, vb0);
                fma2(av[ii][0], p.y, va1); fma2(av[ii][1], p.y, vb1);
            }
        }
    }
    __syncthreads();   // all warps done reading qkv + probs

    // ---- write ao split tiles: hi -> J_ALO, lo -> J_S1 (both dead regions) ----
    {
        const int tl = warp / 3, i0 = (warp % 3) * 8, d0 = lane * 4;
        #pragma unroll
        for (int ii = 0; ii < 8; ii++) {
            float v0, v1, v2, v3;
            up2(av[ii][0], v0, v1);
            up2(av[ii][1], v2, v3);
            uint16_t h0, l0, h1, l1, h2, l2, h3, l3;
            split_bf(v0, h0, l0); split_bf(v1, h1, l1);
            split_bf(v2, h2, l2); split_bf(v3, h3, l3);
            int row = tl * 24 + i0 + ii;
            uint32_t off = (uint32_t)(row * TPAD + d0) * 2;
            *(uint2*)(sm + J_ALO + off) = make_uint2(h0 | ((uint32_t)h1 << 16), h2 | ((uint32_t)h3 << 16));
            *(uint2*)(sm + J_S1 + off)  = make_uint2(l0 | ((uint32_t)l1 << 16), l2 | ((uint32_t)l3 << 16));
        }
    }
    // load Wc tiles into dead qkv region + bc bias
    for (int idx = tid; idx < 2048; idx += 384) {
        int row = idx >> 4, c8 = (idx & 15) * 8;
        uint32_t off = (uint32_t)(row * TPAD + c8) * 2;
        cp16(sb + J_WCHI + off, g_wc_hi + row * 128 + c8);
        cp16(sb + J_WCLO + off, g_wc_lo + row * 128 + c8);
    }
    if (tid < 128) *(float*)(sm + J_BIAS + tid * 4) = g_bc[tid];
    cp_commit();
    cp_wait0();
    __syncthreads();

    // ---- Wc GEMM: fout = ao @ Wc ; 12 warps = 3M(32) x 4N(32) ----
    {
        const int wm0 = (warp % 3) * 32, wn0 = (warp / 3) * 32;
        float acc2[2][4][4];
        #pragma unroll
        for (int i = 0; i < 2; i++)
            #pragma unroll
            for (int j = 0; j < 4; j++)
                #pragma unroll
                for (int q = 0; q < 4; q++) acc2[i][j][q] = 0.f;
        gemm3<2, 2>(sb + J_ALO, sb + J_S1, sb + J_WCHI, sb + J_WCLO, acc2, lane, wm0, wn0);
        stash<2, 2>((float*)(sm + J_STG), acc2, lane, wm0, wn0);
    }
    __syncthreads();

    // ---- output: out = x + fout + bc  (4 t's contiguous -> float4) ----
    {
        const float* stg = (const float*)(sm + J_STG);
        const float* bcs = (const float*)(sm + J_BIAS);
        for (int idx = tid; idx < 3072; idx += 384) {
            int i = idx >> 7, c = idx & 127;
            size_t gb = ((size_t)(b * 3072 + i * 128 + c)) * 4096 + t0;
            float4 xv = *reinterpret_cast<const float4*>(x + gb);
            float bv = bcs[c];
            float4 ov;
            ov.x = xv.x + stg[(0 * 24 + i) * 129 + c] + bv;
            ov.y = xv.y + stg[(1 * 24 + i) * 129 + c] + bv;
            ov.z = xv.z + stg[(2 * 24 + i) * 129 + c] + bv;
            ov.w = xv.w + stg[(3 * 24 + i) * 129 + c] + bv;
            *reinterpret_cast<float4*>(out + gb) = ov;
        }
    }
}

// ================= host =================
extern "C" void kernel_launch(void* const* d_in, const int* in_sizes, int n_in,
                              void* d_out, int out_size)
{
    (void)in_sizes; (void)n_in; (void)out_size;
    const float* x      = (const float*)d_in[0];
    const float* W_tok  = (const float*)d_in[1];
    const float* b_tok  = (const float*)d_in[2];
    const float* g_norm = (const float*)d_in[3];
    const float* W_qkv  = (const float*)d_in[4];
    const float* b_qkv  = (const float*)d_in[5];
    const float* W_proj = (const float*)d_in[6];
    const float* b_proj = (const float*)d_in[7];
    const float* W_from = (const float*)d_in[8];
    const float* b_from = (const float*)d_in[9];
    float* out = (float*)d_out;

    cudaFuncSetAttribute(k1_tok, cudaFuncAttributeMaxDynamicSharedMemorySize, K1_SMEM);
    cudaFuncSetAttribute(k234,   cudaFuncAttributeMaxDynamicSharedMemorySize, K23_SMEM);

    k0a<<<4, 256>>>(W_proj, W_from, b_proj, b_from);
    k0b<<<192, 256>>>(W_tok, W_qkv);
    {
        dim3 g(64, 24, 4);
        k1_tok<<<g, 256, K1_SMEM>>>(x, b_tok, g_norm);
    }
    {
        dim3 g(1024, 4);
        k234<<<g, 384, K23_SMEM>>>(x, b_qkv, out);
    }
}

// round 16
// speedup vs baseline: 1.1509x; 1.1509x over previous
#include <cuda_runtime.h>
#include <cuda_bf16.h>
#include <cstdint>

#define TLEN 4096
#define KJ   24
#define NBATCH 4
#define MTOT (NBATCH * KJ * TLEN)   // 393216 token rows
#define TPAD 136                     // bf16 elems per smem tile row (272B)

// ---------------- device scratch ----------------
__device__ __align__(256) __nv_bfloat16 g_tok_hi[(size_t)MTOT * 128];
__device__ __align__(256) __nv_bfloat16 g_tok_lo[(size_t)MTOT * 128];
__device__ __align__(256) __nv_bfloat16 g_ao_hi[(size_t)MTOT * 128];
__device__ __align__(256) __nv_bfloat16 g_ao_lo[(size_t)MTOT * 128];
__device__ __align__(256) float         g_wc[128 * 128];
__device__ __align__(256) float         g_bc[128];
__device__ __align__(256) float         g_wu[128 * 128];      // M^T in B layout [n][k]
__device__ __align__(256) float         g_w2[128], g_w3[128], g_C[1];
__device__ __align__(256) __nv_bfloat16 g_wtok_hi[128 * 128], g_wtok_lo[128 * 128];
__device__ __align__(256) __nv_bfloat16 g_wu_hi[128 * 128],   g_wu_lo[128 * 128];
__device__ __align__(256) __nv_bfloat16 g_wv_hi[128 * 128],   g_wv_lo[128 * 128];
__device__ __align__(256) __nv_bfloat16 g_wc_hi[128 * 128],   g_wc_lo[128 * 128];

typedef unsigned long long u64;

// ---------------- helpers ----------------
static __device__ __forceinline__ uint32_t s2u(const void* p) {
    uint32_t a;
    asm("{ .reg .u64 t; cvta.to.shared.u64 t, %1; cvt.u32.u64 %0, t; }" : "=r"(a) : "l"(p));
    return a;
}
static __device__ __forceinline__ void cp16(uint32_t dst, const void* src) {
    asm volatile("cp.async.cg.shared.global [%0], [%1], 16;" :: "r"(dst), "l"(src));
}
static __device__ __forceinline__ void cp_commit() {
    asm volatile("cp.async.commit_group;");
}
static __device__ __forceinline__ void cp_wait0() {
    asm volatile("cp.async.wait_group 0;" ::: "memory");
}
template<int N>
static __device__ __forceinline__ void cp_waitg() {
    asm volatile("cp.async.wait_group %0;" :: "n"(N) : "memory");
}
static __device__ __forceinline__ void split_bf(float v, uint16_t& h, uint16_t& l) {
    __nv_bfloat16 hb = __float2bfloat16(v);
    float r = v - __bfloat162float(hb);
    h = __bfloat16_as_ushort(hb);
    l = __bfloat16_as_ushort(__float2bfloat16(r));
}
static __device__ __forceinline__ void fma2(u64& d, u64 a, u64 b) {
    asm("fma.rn.f32x2 %0, %1, %2, %0;" : "+l"(d) : "l"(a), "l"(b));
}
static __device__ __forceinline__ void up2(u64 v, float& a, float& b) {
    asm("mov.b64 {%0, %1}, %2;" : "=f"(a), "=f"(b) : "l"(v));
}
static __device__ __forceinline__ u64 pk2f(float a, float b) {
    u64 r;
    asm("mov.b64 %0, {%1, %2};" : "=l"(r) : "f"(a), "f"(b));
    return r;
}
static __device__ __forceinline__ void ldsm4(uint32_t* r, uint32_t addr) {
    asm volatile("ldmatrix.sync.aligned.m8n8.x4.shared.b16 {%0,%1,%2,%3}, [%4];"
                 : "=r"(r[0]), "=r"(r[1]), "=r"(r[2]), "=r"(r[3]) : "r"(addr));
}
static __device__ __forceinline__ void mma16816(float* c, const uint32_t* a, const uint32_t* b) {
    asm volatile("mma.sync.aligned.m16n8k16.row.col.f32.bf16.bf16.f32 "
                 "{%0,%1,%2,%3}, {%4,%5,%6,%7}, {%8,%9}, {%0,%1,%2,%3};"
                 : "+f"(c[0]), "+f"(c[1]), "+f"(c[2]), "+f"(c[3])
                 : "r"(a[0]), "r"(a[1]), "r"(a[2]), "r"(a[3]), "r"(b[0]), "r"(b[1]));
}

// one K=128 pass of a (MT*16)x(NT*16) warp tile
template<int MT, int NT>
static __device__ __forceinline__ void gemm_pass(uint32_t aBase, uint32_t bBase,
                                                 float acc[MT][2 * NT][4],
                                                 int lane, int m0, int n0) {
    const int ar = m0 + (lane & 15), ac = 8 * (lane >> 4);
    const int br = (lane & 7) + 8 * (lane >> 4), bc = 8 * ((lane >> 3) & 1);
    #pragma unroll
    for (int ks = 0; ks < 8; ks++) {
        uint32_t a[MT][4], b[NT][4];
        #pragma unroll
        for (int mt = 0; mt < MT; mt++)
            ldsm4(a[mt], aBase + (uint32_t)((ar + mt * 16) * TPAD + ks * 16 + ac) * 2);
        #pragma unroll
        for (int nt = 0; nt < NT; nt++)
            ldsm4(b[nt], bBase + (uint32_t)((n0 + nt * 16 + br) * TPAD + ks * 16 + bc) * 2);
        #pragma unroll
        for (int mt = 0; mt < MT; mt++)
            #pragma unroll
            for (int nt = 0; nt < NT; nt++) {
                mma16816(acc[mt][nt * 2],     a[mt], &b[nt][0]);
                mma16816(acc[mt][nt * 2 + 1], a[mt], &b[nt][2]);
            }
    }
}
template<int MT, int NT>
static __device__ __forceinline__ void gemm3(uint32_t aHi, uint32_t aLo, uint32_t bHi,
                                             uint32_t bLo, float acc[MT][2 * NT][4],
                                             int lane, int m0, int n0) {
    gemm_pass<MT, NT>(aHi, bHi, acc, lane, m0, n0);
    gemm_pass<MT, NT>(aHi, bLo, acc, lane, m0, n0);
    gemm_pass<MT, NT>(aLo, bHi, acc, lane, m0, n0);
}
template<int MT, int NT>
static __device__ __forceinline__ void stash(float* stg, const float acc[MT][2 * NT][4],
                                             int lane, int m0, int n0) {
    const int r = m0 + (lane >> 2), cq = (lane & 3) * 2;
    #pragma unroll
    for (int mt = 0; mt < MT; mt++)
        #pragma unroll
        for (int n8 = 0; n8 < 2 * NT; n8++) {
            const float* c = acc[mt][n8];
            int row = r + mt * 16, col = n0 + n8 * 8 + cq;
            stg[row * 129 + col]           = c[0];
            stg[row * 129 + col + 1]       = c[1];
            stg[(row + 8) * 129 + col]     = c[2];
            stg[(row + 8) * 129 + col + 1] = c[3];
        }
}

// ================= K0a: Wc = W_proj @ W_from, bc = b_proj@W_from + b_from =========
__global__ __launch_bounds__(256) void k0a(const float* __restrict__ Wp,
                                           const float* __restrict__ Wf,
                                           const float* __restrict__ bp,
                                           const float* __restrict__ bf) {
    __shared__ float swp[32 * 128];
    const int tid = threadIdx.x, r0 = blockIdx.x * 32;
    for (int i = tid; i < 32 * 128; i += 256) swp[i] = Wp[(r0 + (i >> 7)) * 128 + (i & 127)];
    __syncthreads();
    const int n = tid & 127, rb = tid >> 7;
    float acc[16];
    #pragma unroll
    for (int q = 0; q < 16; q++) acc[q] = 0.f;
    for (int m = 0; m < 128; m++) {
        float wf = Wf[m * 128 + n];
        #pragma unroll
        for (int q = 0; q < 16; q++) acc[q] += swp[(rb * 16 + q) * 128 + m] * wf;
    }
    #pragma unroll
    for (int q = 0; q < 16; q++) g_wc[(r0 + rb * 16 + q) * 128 + n] = acc[q];
    if (blockIdx.x == 0 && tid < 128) {
        float a = bf[tid];
        for (int m = 0; m < 128; m++) a += bp[m] * Wf[m * 128 + tid];
        g_bc[tid] = a;
    }
}

// ================= K0c: g_wu[n][k] = sum_d Wq[k][d]*Wk[n][d]; w2, w3, C ==========
__global__ __launch_bounds__(256) void k0c(const float* __restrict__ Wqkv,
                                           const float* __restrict__ bqkv) {
    __shared__ float swq[32 * 128];
    const int tid = threadIdx.x, r0 = blockIdx.x * 32;   // k-range
    for (int i = tid; i < 32 * 128; i += 256)
        swq[i] = Wqkv[(size_t)(r0 + (i >> 7)) * 384 + (i & 127)];
    __syncthreads();
    const int n = tid & 127, kb = tid >> 7;
    float acc[16];
    #pragma unroll
    for (int q = 0; q < 16; q++) acc[q] = 0.f;
    for (int d = 0; d < 128; d++) {
        float wk = Wqkv[(size_t)n * 384 + 128 + d];
        #pragma unroll
        for (int q = 0; q < 16; q++) acc[q] += swq[(kb * 16 + q) * 128 + d] * wk;
    }
    #pragma unroll
    for (int q = 0; q < 16; q++) g_wu[n * 128 + r0 + kb * 16 + q] = acc[q];
    if (blockIdx.x == 0 && tid < 128) {
        float a2 = 0.f, a3 = 0.f;
        for (int d = 0; d < 128; d++) {
            a2 += Wqkv[(size_t)tid * 384 + d] * bqkv[128 + d];
            a3 += Wqkv[(size_t)tid * 384 + 128 + d] * bqkv[d];
        }
        g_w2[tid] = a2;
        g_w3[tid] = a3;
        if (tid == 0) {
            float c = 0.f;
            for (int d = 0; d < 128; d++) c += bqkv[d] * bqkv[128 + d];
            g_C[0] = c;
        }
    }
}

// ================= K0b: split weights (Wtok, Wc, Wu, Wv) =================
__global__ __launch_bounds__(256) void k0b(const float* __restrict__ Wt,
                                           const float* __restrict__ Wq) {
    const int i = blockIdx.x * 256 + threadIdx.x;
    uint16_t h, l;
    if (i < 16384) {
        int n = i >> 7, k = i & 127;
        split_bf(Wt[k * 128 + n], h, l);
        g_wtok_hi[i] = __ushort_as_bfloat16(h); g_wtok_lo[i] = __ushort_as_bfloat16(l);
        split_bf(g_wc[k * 128 + n], h, l);
        g_wc_hi[i] = __ushort_as_bfloat16(h);   g_wc_lo[i] = __ushort_as_bfloat16(l);
        split_bf(g_wu[i], h, l);                // already [n][k]
        g_wu_hi[i] = __ushort_as_bfloat16(h);   g_wu_lo[i] = __ushort_as_bfloat16(l);
        split_bf(Wq[(size_t)k * 384 + 256 + n], h, l);   // Wv as B[n][k]
        g_wv_hi[i] = __ushort_as_bfloat16(h);   g_wv_lo[i] = __ushort_as_bfloat16(l);
    }
}

// ================= K1: tok = x^T @ W_tok + b, RMSNorm, split-store ===============
#define K1_BIAS 0
#define K1_G    512
#define K1_AXS  1024
#define K1_AHI  35840
#define K1_ALO  53248
#define K1_BHI  70656
#define K1_BLO  88064
#define K1_SMEM 105472

__global__ __launch_bounds__(256, 2)
void k1_tok(const float* __restrict__ x, const float* __restrict__ b_tok,
            const float* __restrict__ g_norm) {
    extern __shared__ char sm[];
    const int tid = threadIdx.x, warp = tid >> 5, lane = tid & 31;
    const int b = blockIdx.z, kj = blockIdx.y, t0 = blockIdx.x * 64;
    const uint32_t sb = s2u(sm);

    for (int idx = tid; idx < 2048; idx += 256) {
        int c = idx >> 4, t16 = (idx & 15) * 4;
        const float* src = x + ((size_t)(b * 3072 + kj * 128 + c)) * 4096 + t0 + t16;
        cp16(sb + K1_AXS + (uint32_t)(c * 68 + t16) * 4, src);
    }
    for (int idx = tid; idx < 1024; idx += 256) {
        int row = idx >> 4, c8 = (idx & 15) * 8;
        uint32_t off = (uint32_t)(row * TPAD + c8) * 2;
        cp16(sb + K1_BHI + off, g_wtok_hi + row * 128 + c8);
        cp16(sb + K1_BLO + off, g_wtok_lo + row * 128 + c8);
    }
    if (tid < 128) {
        *(float*)(sm + K1_BIAS + tid * 4) = b_tok[tid];
        *(float*)(sm + K1_G + tid * 4)    = g_norm[tid];
    }
    cp_commit();
    cp_wait0();
    __syncthreads();

    {
        const int t = tid & 63, quarter = tid >> 6;
        const float* ax = (const float*)(sm + K1_AXS);
        for (int c4 = quarter * 8; c4 < quarter * 8 + 8; c4++) {
            int c = c4 * 4;
            float v0 = ax[(c + 0) * 68 + t], v1 = ax[(c + 1) * 68 + t];
            float v2 = ax[(c + 2) * 68 + t], v3 = ax[(c + 3) * 68 + t];
            uint16_t h0, l0, h1, l1, h2, l2, h3, l3;
            split_bf(v0, h0, l0); split_bf(v1, h1, l1);
            split_bf(v2, h2, l2); split_bf(v3, h3, l3);
            uint32_t off = (uint32_t)(t * TPAD + c) * 2;
            *(uint2*)(sm + K1_AHI + off) = make_uint2(h0 | ((uint32_t)h1 << 16), h2 | ((uint32_t)h3 << 16));
            *(uint2*)(sm + K1_ALO + off) = make_uint2(l0 | ((uint32_t)l1 << 16), l2 | ((uint32_t)l3 << 16));
        }
    }
    __syncthreads();

    const int m0 = (warp & 3) * 16, n0 = (warp >> 2) * 32;
    for (int nc = 0; nc < 2; nc++) {
        float acc[1][4][4];
        #pragma unroll
        for (int j = 0; j < 4; j++)
            #pragma unroll
            for (int q = 0; q < 4; q++) acc[0][j][q] = 0.f;
        gemm3<1, 2>(sb + K1_AHI, sb + K1_ALO, sb + K1_BHI, sb + K1_BLO, acc, lane, m0, n0);
        stash<1, 2>((float*)(sm + K1_AXS), acc, lane, m0, nc * 64 + n0);
        if (nc == 0) {
            __syncthreads();
            for (int idx = tid; idx < 1024; idx += 256) {
                int row = idx >> 4, c8 = (idx & 15) * 8;
                uint32_t off = (uint32_t)(row * TPAD + c8) * 2;
                cp16(sb + K1_BHI + off, g_wtok_hi + (64 + row) * 128 + c8);
                cp16(sb + K1_BLO + off, g_wtok_lo + (64 + row) * 128 + c8);
            }
            cp_commit();
            cp_wait0();
            __syncthreads();
        }
    }
    __syncthreads();

    uint32_t* shi = (uint32_t*)(sm + K1_AHI);
    uint32_t* slo = (uint32_t*)(sm + K1_ALO);
    {
        const int row = tid >> 2, sub = tid & 3;
        const float* stg  = (const float*)(sm + K1_AXS);
        const float* bias = (const float*)(sm + K1_BIAS);
        const float* gw   = (const float*)(sm + K1_G);
        float ss = 0.f;
        #pragma unroll 8
        for (int c = sub * 32; c < sub * 32 + 32; c++) {
            float v = stg[row * 129 + c] + bias[c];
            ss += v * v;
        }
        ss += __shfl_xor_sync(0xffffffffu, ss, 1);
        ss += __shfl_xor_sync(0xffffffffu, ss, 2);
        float inv = rsqrtf(ss * (1.0f / 128.0f) + 1e-5f);
        #pragma unroll 4
        for (int c2 = 0; c2 < 16; c2++) {
            int c = sub * 32 + c2 * 2;
            float v0 = (stg[row * 129 + c]     + bias[c])     * inv * gw[c];
            float v1 = (stg[row * 129 + c + 1] + bias[c + 1]) * inv * gw[c + 1];
            uint16_t h0, l0, h1, l1;
            split_bf(v0, h0, l0); split_bf(v1, h1, l1);
            shi[row * 65 + sub * 16 + c2] = h0 | ((uint32_t)h1 << 16);
            slo[row * 65 + sub * 16 + c2] = l0 | ((uint32_t)l1 << 16);
        }
    }
    __syncthreads();
    {
        uint32_t* dhi = (uint32_t*)g_tok_hi;
        uint32_t* dlo = (uint32_t*)g_tok_lo;
        for (int idx = tid; idx < 4096; idx += 256) {
            int row = idx >> 6, w = idx & 63;
            size_t rid = ((size_t)b * 4096 + t0 + row) * 24 + kj;
            dhi[rid * 64 + w] = shi[row * 65 + w];
            dlo[rid * 64 + w] = slo[row * 65 + w];
        }
    }
}

// ================= K23: fused u/v GEMM (4 chunks) + attention ====================
// scores via s = u.tok + t2_i + t3_j + C  (u = tok @ WqWk^T)
#define QS2 262
#define PRS 52
#define J_BIAS 0                     // 256 f32 (0 for u cols, bv for v cols)
#define J_W23  1024                  // 256 f32 (w2 | w3)
#define J_T23  2048                  // 192 f32 (t2 | t3) + C at +768
#define J_AHI  3072                  // [96][TPAD] bf16 = 26112  (stays alive)
#define J_ALO  29184                 // [96][TPAD] = 26112
#define J_S0   55296                 // B slot0 = 17408
#define J_S1   72704                 // B slot1 = 17408
#define J_UV   90112                 // f32 [96][QS2] = 100608
#define K23_SMEM 190720
#define J_PROBS J_S0                 // probs overlay S0+S1 after GEMM (19968 B)

__global__ __launch_bounds__(384, 1)
void k23(const float* __restrict__ b_qkv) {
    extern __shared__ char sm[];
    const int tid = threadIdx.x, warp = tid >> 5, lane = tid & 31;
    const int b = blockIdx.y, t0 = blockIdx.x * 4;
    const size_t rid0 = ((size_t)b * 4096 + t0) * 24;
    const uint32_t sb = s2u(sm);

    const __nv_bfloat16* hi_src[4] = { g_wu_hi, g_wu_hi + 64 * 128,
                                       g_wv_hi, g_wv_hi + 64 * 128 };
    const __nv_bfloat16* lo_src[4] = { g_wu_lo, g_wu_lo + 64 * 128,
                                       g_wv_lo, g_wv_lo + 64 * 128 };

    // initial loads: A tiles + B hi(0)->S0 + B lo(0)->S1 + bias/w23/C
    for (int idx = tid; idx < 1536; idx += 384) {
        int row = idx >> 4, c8 = (idx & 15) * 8;
        uint32_t off = (uint32_t)(row * TPAD + c8) * 2;
        cp16(sb + J_AHI + off, g_tok_hi + (rid0 + row) * 128 + c8);
        cp16(sb + J_ALO + off, g_tok_lo + (rid0 + row) * 128 + c8);
    }
    for (int idx = tid; idx < 1024; idx += 384) {
        int row = idx >> 4, c8 = (idx & 15) * 8;
        uint32_t off = (uint32_t)(row * TPAD + c8) * 2;
        cp16(sb + J_S0 + off, hi_src[0] + row * 128 + c8);
        cp16(sb + J_S1 + off, lo_src[0] + row * 128 + c8);
    }
    if (tid < 256) {
        *(float*)(sm + J_BIAS + tid * 4) = (tid < 128) ? 0.f : b_qkv[256 + tid - 128];
        *(float*)(sm + J_W23 + tid * 4)  = (tid < 128) ? g_w2[tid] : g_w3[tid - 128];
    }
    if (tid == 256) *(float*)(sm + J_T23 + 768) = g_C[0];
    cp_commit();
    cp_wait0();
    __syncthreads();

    // 12 warps = 3M(32) x 4N(16)
    const int m0 = (warp % 3) * 32, n0 = (warp / 3) * 16;
    const int ar = m0 + (lane & 15), ac = 8 * (lane >> 4);
    const int br = (lane & 7) + 8 * (lane >> 4), bc = 8 * ((lane >> 3) & 1);
    float* uv = (float*)(sm + J_UV);
    const float* bias = (const float*)(sm + J_BIAS);

    // hoist A_hi fragments (64 regs); A_hi smem stays alive for scores
    uint32_t ahi[2][8][4];
    #pragma unroll
    for (int ks = 0; ks < 8; ks++) {
        ldsm4(ahi[0][ks], sb + J_AHI + (uint32_t)(ar * TPAD + ks * 16 + ac) * 2);
        ldsm4(ahi[1][ks], sb + J_AHI + (uint32_t)((ar + 16) * TPAD + ks * 16 + ac) * 2);
    }

    for (int nc = 0; nc < 4; nc++) {
        if (nc > 0) {
            cp_waitg<1>();      // hi(nc) landed in slot0
            __syncthreads();
        }

        float acc[2][2][4];
        #pragma unroll
        for (int i = 0; i < 2; i++)
            #pragma unroll
            for (int j = 0; j < 2; j++)
                #pragma unroll
                for (int q = 0; q < 4; q++) acc[i][j][q] = 0.f;

        // pass1: hi*hi (A from regs, B slot0)
        #pragma unroll
        for (int ks = 0; ks < 8; ks++) {
            uint32_t bfr[4];
            ldsm4(bfr, sb + J_S0 + (uint32_t)((n0 + br) * TPAD + ks * 16 + bc) * 2);
            mma16816(acc[0][0], ahi[0][ks], &bfr[0]);
            mma16816(acc[0][1], ahi[0][ks], &bfr[2]);
            mma16816(acc[1][0], ahi[1][ks], &bfr[0]);
            mma16816(acc[1][1], ahi[1][ks], &bfr[2]);
        }
        // pass2: lo*hi (A_lo smem, B slot0)
        #pragma unroll
        for (int ks = 0; ks < 8; ks++) {
            uint32_t a0[4], a1[4], bfr[4];
            ldsm4(a0, sb + J_ALO + (uint32_t)(ar * TPAD + ks * 16 + ac) * 2);
            ldsm4(a1, sb + J_ALO + (uint32_t)((ar + 16) * TPAD + ks * 16 + ac) * 2);
            ldsm4(bfr, sb + J_S0 + (uint32_t)((n0 + br) * TPAD + ks * 16 + bc) * 2);
            mma16816(acc[0][0], a0, &bfr[0]);
            mma16816(acc[0][1], a0, &bfr[2]);
            mma16816(acc[1][0], a1, &bfr[0]);
            mma16816(acc[1][1], a1, &bfr[2]);
        }
        __syncthreads();       // all warps done with slot0

        if (nc < 3) {          // prefetch hi(nc+1) -> slot0, overlaps pass3
            for (int idx = tid; idx < 1024; idx += 384) {
                int row = idx >> 4, c8 = (idx & 15) * 8;
                cp16(sb + J_S0 + (uint32_t)(row * TPAD + c8) * 2,
                     hi_src[nc + 1] + row * 128 + c8);
            }
            cp_commit();
            cp_waitg<1>();     // lo(nc) landed in slot1
        } else {
            cp_waitg<0>();
        }
        __syncthreads();

        // pass3: hi*lo (A from regs, B slot1)
        #pragma unroll
        for (int ks = 0; ks < 8; ks++) {
            uint32_t bfr[4];
            ldsm4(bfr, sb + J_S1 + (uint32_t)((n0 + br) * TPAD + ks * 16 + bc) * 2);
            mma16816(acc[0][0], ahi[0][ks], &bfr[0]);
            mma16816(acc[0][1], ahi[0][ks], &bfr[2]);
            mma16816(acc[1][0], ahi[1][ks], &bfr[0]);
            mma16816(acc[1][1], ahi[1][ks], &bfr[2]);
        }

        // epilogue -> uv smem (+bias), float2 stores
        {
            const int r = m0 + (lane >> 2), cq = (lane & 3) * 2;
            #pragma unroll
            for (int mt = 0; mt < 2; mt++)
                #pragma unroll
                for (int n8 = 0; n8 < 2; n8++) {
                    const float* c = acc[mt][n8];
                    int col = nc * 64 + n0 + n8 * 8 + cq;
                    int row = r + mt * 16;
                    float b0 = bias[col], b1 = bias[col + 1];
                    *(float2*)(uv + row * QS2 + col)       = make_float2(c[0] + b0, c[1] + b1);
                    *(float2*)(uv + (row + 8) * QS2 + col) = make_float2(c[2] + b0, c[3] + b1);
                }
        }
        __syncthreads();       // all warps done with slot1

        if (nc < 3) {          // prefetch lo(nc+1) -> slot1
            for (int idx = tid; idx < 1024; idx += 384) {
                int row = idx >> 4, c8 = (idx & 15) * 8;
                cp16(sb + J_S1 + (uint32_t)(row * TPAD + c8) * 2,
                     lo_src[nc + 1] + row * 128 + c8);
            }
            cp_commit();
        }
    }
    cp_wait0();

    // ---- t2/t3 per row ----
    if (tid < 192) {
        const int r = tid % 96, which = tid / 96;
        const float* w = (const float*)(sm + J_W23) + which * 128;
        float a = 0.f;
        #pragma unroll 8
        for (int c2 = 0; c2 < 64; c2++) {
            uint32_t h = *(const uint32_t*)(sm + J_AHI + (uint32_t)(r * TPAD + 2 * c2) * 2);
            uint32_t l = *(const uint32_t*)(sm + J_ALO + (uint32_t)(r * TPAD + 2 * c2) * 2);
            float f0 = __uint_as_float(h << 16) + __uint_as_float(l << 16);
            float f1 = __uint_as_float(h & 0xFFFF0000u) + __uint_as_float(l & 0xFFFF0000u);
            a += f0 * w[2 * c2] + f1 * w[2 * c2 + 1];
        }
        ((float*)(sm + J_T23))[which * 96 + r] = a;
    }
    __syncthreads();

    // ---- scores: s = u.tok + t2_i + t3_j + C ; 2q x 4j tiles, 288 tiles ----
    float* probs = (float*)(sm + J_PROBS);
    if (tid < 288) {
        int tl = tid / 72, rem = tid - tl * 72;
        int ti = rem / 6, tj = rem - ti * 6;
        int i = 2 * ti, j = 4 * tj;
        int ig = tl * 24 + i, jg = tl * 24 + j;
        const u64* u0 = reinterpret_cast<const u64*>(uv + ig * QS2);
        const u64* u1 = reinterpret_cast<const u64*>(uv + (ig + 1) * QS2);
        u64 a0[4] = {0ull, 0ull, 0ull, 0ull};
        u64 a1[4] = {0ull, 0ull, 0ull, 0ull};
        #pragma unroll 4
        for (int c2 = 0; c2 < 64; c2++) {
            u64 qa = u0[c2], qb = u1[c2];
            #pragma unroll
            for (int jj = 0; jj < 4; jj++) {
                uint32_t h = *(const uint32_t*)(sm + J_AHI + (uint32_t)((jg + jj) * TPAD + 2 * c2) * 2);
                uint32_t l = *(const uint32_t*)(sm + J_ALO + (uint32_t)((jg + jj) * TPAD + 2 * c2) * 2);
                float f0 = __uint_as_float(h << 16) + __uint_as_float(l << 16);
                float f1 = __uint_as_float(h & 0xFFFF0000u) + __uint_as_float(l & 0xFFFF0000u);
                u64 tv = pk2f(f0, f1);
                fma2(a0[jj], qa, tv);
                fma2(a1[jj], qb, tv);
            }
        }
        const float SC = 0.08838834764831845f;
        const float* t2 = (const float*)(sm + J_T23);
        const float* t3 = t2 + 96;
        const float C = *(const float*)(sm + J_T23 + 768);
        float t2i0 = t2[ig] + C, t2i1 = t2[ig + 1] + C;
        float* pr = probs + ig * PRS;
        float s0, s1;
        #pragma unroll
        for (int jj = 0; jj < 4; jj++) {
            float t3j = t3[jg + jj];
            up2(a0[jj], s0, s1); pr[2 * (j + jj)]       = (s0 + s1 + t2i0 + t3j) * SC;
            up2(a1[jj], s0, s1); pr[PRS + 2 * (j + jj)] = (s0 + s1 + t2i1 + t3j) * SC;
        }
    }
    __syncthreads();

    if (tid < 96) {
        int tl = tid / 24, i = tid - tl * 24;
        float* pr = probs + (tl * 24 + i) * PRS;
        float m = pr[0];
        #pragma unroll
        for (int j = 1; j < 24; j++) m = fmaxf(m, pr[2 * j]);
        float s = 0.f, e[24];
        #pragma unroll
        for (int j = 0; j < 24; j++) { e[j] = __expf(pr[2 * j] - m); s += e[j]; }
        float inv = 1.0f / s;
        #pragma unroll
        for (int j = 0; j < 24; j++) {
            float p = e[j] * inv;
            *reinterpret_cast<float2*>(pr + 2 * j) = make_float2(p, p);
        }
    }
    __syncthreads();

    // AV: 12 warps: tl = warp/3, 8 joints per warp; v at uv cols 128..255
    {
        const int tl = warp / 3, i0 = (warp % 3) * 8, d0 = lane * 4;
        u64 acc[8][2];
        #pragma unroll
        for (int ii = 0; ii < 8; ii++) { acc[ii][0] = 0ull; acc[ii][1] = 0ull; }
        const float* pr0 = probs + (tl * 24 + i0) * PRS;
        #pragma unroll 3
        for (int j2 = 0; j2 < 12; j2++) {
            const u64* vp0 = reinterpret_cast<const u64*>(uv + (tl * 24 + 2 * j2) * QS2 + 128 + d0);
            const u64* vp1 = reinterpret_cast<const u64*>(uv + (tl * 24 + 2 * j2 + 1) * QS2 + 128 + d0);
            u64 va0 = vp0[0], vb0 = vp0[1];
            u64 va1 = vp1[0], vb1 = vp1[1];
            #pragma unroll
            for (int ii = 0; ii < 8; ii++) {
                ulonglong2 p = *reinterpret_cast<const ulonglong2*>(pr0 + ii * PRS + 4 * j2);
                fma2(acc[ii][0], p.x, va0); fma2(acc[ii][1], p.x, vb0);
                fma2(acc[ii][0], p.y, va1); fma2(acc[ii][1], p.y, vb1);
            }
        }
        uint32_t* dhi = (uint32_t*)g_ao_hi;
        uint32_t* dlo = (uint32_t*)g_ao_lo;
        #pragma unroll
        for (int ii = 0; ii < 8; ii++) {
            float v0, v1, v2, v3;
            up2(acc[ii][0], v0, v1);
            up2(acc[ii][1], v2, v3);
            uint16_t h0, l0, h1, l1, h2, l2, h3, l3;
            split_bf(v0, h0, l0); split_bf(v1, h1, l1);
            split_bf(v2, h2, l2); split_bf(v3, h3, l3);
            size_t rid = rid0 + tl * 24 + i0 + ii;
            dhi[rid * 64 + lane * 2]     = h0 | ((uint32_t)h1 << 16);
            dhi[rid * 64 + lane * 2 + 1] = h2 | ((uint32_t)h3 << 16);
            dlo[rid * 64 + lane * 2]     = l0 | ((uint32_t)l1 << 16);
            dlo[rid * 64 + lane * 2 + 1] = l2 | ((uint32_t)l3 << 16);
        }
    }
}

// ================= K4: out = x + ao @ Wc + bc (transposed store) =================
#define K4_BIAS 0
#define K4_STG  512
#define K4_AHI  33536
#define K4_ALO  50944
#define K4_BHI  68352
#define K4_BLO  85760
#define K4_SMEM 103168

__global__ __launch_bounds__(256, 2)
void k4_out(const float* __restrict__ x, float* __restrict__ out) {
    extern __shared__ char sm[];
    const int tid = threadIdx.x, warp = tid >> 5, lane = tid & 31;
    const int b = blockIdx.z, kj = blockIdx.y, t0 = blockIdx.x * 64;
    const uint32_t sb = s2u(sm);

    for (int idx = tid; idx < 1024; idx += 256) {
        int row = idx >> 4, c8 = (idx & 15) * 8;
        uint32_t off = (uint32_t)(row * TPAD + c8) * 2;
        size_t rid = ((size_t)b * 4096 + t0 + row) * 24 + kj;
        cp16(sb + K4_AHI + off, g_ao_hi + rid * 128 + c8);
        cp16(sb + K4_ALO + off, g_ao_lo + rid * 128 + c8);
    }
    for (int idx = tid; idx < 1024; idx += 256) {
        int row = idx >> 4, c8 = (idx & 15) * 8;
        uint32_t off = (uint32_t)(row * TPAD + c8) * 2;
        cp16(sb + K4_BHI + off, g_wc_hi + row * 128 + c8);
        cp16(sb + K4_BLO + off, g_wc_lo + row * 128 + c8);
    }
    if (tid < 128) *(float*)(sm + K4_BIAS + tid * 4) = g_bc[tid];
    cp_commit();
    cp_wait0();
    __syncthreads();

    const int m0 = (warp & 3) * 16, n0 = (warp >> 2) * 32;
    for (int nc = 0; nc < 2; nc++) {
        float acc[1][4][4];
        #pragma unroll
        for (int j = 0; j < 4; j++)
            #pragma unroll
            for (int q = 0; q < 4; q++) acc[0][j][q] = 0.f;
        gemm3<1, 2>(sb + K4_AHI, sb + K4_ALO, sb + K4_BHI, sb + K4_BLO, acc, lane, m0, n0);
        stash<1, 2>((float*)(sm + K4_STG), acc, lane, m0, nc * 64 + n0);
        if (nc == 0) {
            __syncthreads();
            for (int idx = tid; idx < 1024; idx += 256) {
                int row = idx >> 4, c8 = (idx & 15) * 8;
                uint32_t off = (uint32_t)(row * TPAD + c8) * 2;
                cp16(sb + K4_BHI + off, g_wc_hi + (64 + row) * 128 + c8);
                cp16(sb + K4_BLO + off, g_wc_lo + (64 + row) * 128 + c8);
            }
            cp_commit();
            cp_wait0();
            __syncthreads();
        }
    }
    __syncthreads();

    {
        const float* stg  = (const float*)(sm + K4_STG);
        const float* bias = (const float*)(sm + K4_BIAS);
        for (int o = tid; o < 2048; o += 256) {
            int c = o >> 4, tq = o & 15;
            float bc = bias[c];
            size_t gb = ((size_t)(b * 3072 + kj * 128 + c)) * 4096 + t0;
            #pragma unroll
            for (int j = 0; j < 4; j++) {
                int t = tq + 16 * j;
                out[gb + t] = x[gb + t] + stg[t * 129 + c] + bc;
            }
        }
    }
}

// ================= host =================
extern "C" void kernel_launch(void* const* d_in, const int* in_sizes, int n_in,
                              void* d_out, int out_size)
{
    (void)in_sizes; (void)n_in; (void)out_size;
    const float* x      = (const float*)d_in[0];
    const float* W_tok  = (const float*)d_in[1];
    const float* b_tok  = (const float*)d_in[2];
    const float* g_norm = (const float*)d_in[3];
    const float* W_qkv  = (const float*)d_in[4];
    const float* b_qkv  = (const float*)d_in[5];
    const float* W_proj = (const float*)d_in[6];
    const float* b_proj = (const float*)d_in[7];
    const float* W_from = (const float*)d_in[8];
    const float* b_from = (const float*)d_in[9];
    float* out = (float*)d_out;

    cudaFuncSetAttribute(k1_tok, cudaFuncAttributeMaxDynamicSharedMemorySize, K1_SMEM);
    cudaFuncSetAttribute(k23,    cudaFuncAttributeMaxDynamicSharedMemorySize, K23_SMEM);
    cudaFuncSetAttribute(k4_out, cudaFuncAttributeMaxDynamicSharedMemorySize, K4_SMEM);

    k0a<<<4, 256>>>(W_proj, W_from, b_proj, b_from);
    k0c<<<4, 256>>>(W_qkv, b_qkv);
    k0b<<<64, 256>>>(W_tok, W_qkv);
    {
        dim3 g(64, 24, 4);
        k1_tok<<<g, 256, K1_SMEM>>>(x, b_tok, g_norm);
    }
    {
        dim3 g(1024, 4);
        k23<<<g, 384, K23_SMEM>>>(b_qkv);
    }
    {
        dim3 g(64, 24, 4);
        k4_out<<<g, 256, K4_SMEM>>>(x, out);
    }
}